// round 6
// baseline (speedup 1.0000x reference)
#include <cuda_runtime.h>
#include <cuda_fp16.h>
#include <mma.h>

using namespace nvcuda;

#define NN 50000
#define NE 1600000
#define CD 128      // HEADS * OUT_F
#define HEADS 4
#define PAD 128     // ELL row width; P(deg>128) ~ 1e-40 for Poisson(32)

// ---------------- device-global scratch (no allocations allowed) ------------
__device__ __half g_h16[(size_t)NN * CD];   // 12.8 MB fp16 features
__device__ float  g_esrc[NN * HEADS];
__device__ float  g_edst[NN * HEADS];
__device__ int    g_cursor[NN];
__device__ int    g_ell[(size_t)NN * PAD];  // 25.6 MB ELL neighbor lists

// ---------------- static host resources --------------------------------------
static cudaStream_t s_side = 0;
static cudaEvent_t  s_fork = 0, s_join = 0;
namespace {
struct StreamInit {
    StreamInit() {
        cudaStreamCreateWithFlags(&s_side, cudaStreamNonBlocking);
        cudaEventCreateWithFlags(&s_fork, cudaEventDisableTiming);
        cudaEventCreateWithFlags(&s_join, cudaEventDisableTiming);
    }
};
StreamInit s_init_;
}

// ---------------- tf32 tensor-core GEMM + logits -----------------------------
// 128 threads (4 warps). Block tile 64 rows x 128 cols, K=128 in 4 chunks of 32.
__global__ __launch_bounds__(128) void k_gemm(const float* __restrict__ x,
                                              const float* __restrict__ W,
                                              const float* __restrict__ att) {
    __shared__ float sm[8192];                 // 32 KB (union mainloop/epilogue)
    float* xs = sm;                            // 64*32
    float* Ws = sm + 2048;                     // 32*128

    const int t = threadIdx.x;
    const int w = t >> 5, lane = t & 31;
    const int R0 = blockIdx.x * 64;

    wmma::fragment<wmma::accumulator, 16, 16, 8, float> acc[8];
#pragma unroll
    for (int c = 0; c < 8; c++) wmma::fill_fragment(acc[c], 0.f);

    for (int kc = 0; kc < 4; kc++) {
        __syncthreads();
#pragma unroll
        for (int j = 0; j < 4; j++) {
            int i = t + 128 * j;
            int row = i >> 3, kq = i & 7;
            int n = R0 + row;
            float4 v = (n < NN) ? __ldg((const float4*)&x[(size_t)n * CD + kc * 32 + kq * 4])
                                : make_float4(0.f, 0.f, 0.f, 0.f);
            *(float4*)&xs[row * 32 + kq * 4] = v;
        }
#pragma unroll
        for (int j = 0; j < 8; j++) {
            int i = t + 128 * j;
            int kr = i >> 5, c4 = i & 31;
            *(float4*)&Ws[kr * 128 + c4 * 4] =
                __ldg((const float4*)&W[(size_t)(kc * 32 + kr) * CD + c4 * 4]);
        }
        __syncthreads();

#pragma unroll
        for (int k0 = 0; k0 < 32; k0 += 8) {
            wmma::fragment<wmma::matrix_a, 16, 16, 8, wmma::precision::tf32, wmma::row_major> af;
            wmma::load_matrix_sync(af, &xs[w * 16 * 32 + k0], 32);
#pragma unroll
            for (int i = 0; i < af.num_elements; i++)
                af.x[i] = wmma::__float_to_tf32(af.x[i]);
#pragma unroll
            for (int c = 0; c < 8; c++) {
                wmma::fragment<wmma::matrix_b, 16, 16, 8, wmma::precision::tf32, wmma::row_major> bf;
                wmma::load_matrix_sync(bf, &Ws[k0 * 128 + c * 16], 128);
#pragma unroll
                for (int i = 0; i < bf.num_elements; i++)
                    bf.x[i] = wmma::__float_to_tf32(bf.x[i]);
                wmma::mma_sync(acc[c], af, bf, acc[c]);
            }
        }
    }

    __syncthreads();
    float* ep = sm + w * 2048;                 // 16 x 128 per warp
#pragma unroll
    for (int c = 0; c < 8; c++)
        wmma::store_matrix_sync(&ep[c * 16], acc[c], 128, wmma::mem_row_major);
    __syncwarp();

#pragma unroll
    for (int rr = 0; rr < 16; rr++) {
        int n = R0 + w * 16 + rr;
        if (n >= NN) break;
        const float* rowp = &ep[rr * 128 + lane * 4];
        __half2 h0 = __floats2half2_rn(rowp[0], rowp[1]);
        __half2 h1 = __floats2half2_rn(rowp[2], rowp[3]);
        uint2 pk;
        pk.x = *(const unsigned*)&h0;
        pk.y = *(const unsigned*)&h1;
        ((uint2*)&g_h16[(size_t)n * CD])[lane] = pk;
    }
#pragma unroll
    for (int q = 0; q < 2; q++) {
        int p = lane + 32 * q;
        int rr = p >> 2, hd = p & 3;
        int n = R0 + w * 16 + rr;
        if (n >= NN) continue;
        const float* rowp = &ep[rr * 128 + hd * 32];
        float es = 0.f, ed = 0.f;
#pragma unroll
        for (int c = 0; c < 32; c++) {
            float v = rowp[c];
            es += v * __ldg(&att[hd * 64 + c]);
            ed += v * __ldg(&att[hd * 64 + 32 + c]);
        }
        g_esrc[n * HEADS + hd] = es;
        g_edst[n * HEADS + hd] = ed;
    }
}

// ---------------- ELL build: single pass, inline dtype detect ----------------
__global__ void k_fill(const int* __restrict__ idx32) {
    int e = 2 * (blockIdx.x * blockDim.x + threadIdx.x);
    if (e >= NE) return;
    // int64 indices < 50000 => high words zero; two-word test, fp prob ~4e-10
    const bool is64 = (__ldg(&idx32[1]) == 0) && (__ldg(&idx32[3]) == 0);
    int r0, r1, c0, c1;
    if (is64) {
        int4 rv = __ldg((const int4*)&idx32[2 * e]);
        int4 cv = __ldg((const int4*)&idx32[2 * (NE + e)]);
        r0 = rv.x; r1 = rv.z; c0 = cv.x; c1 = cv.z;
    } else {
        int2 rv = __ldg((const int2*)&idx32[e]);
        int2 cv = __ldg((const int2*)&idx32[NE + e]);
        r0 = rv.x; r1 = rv.y; c0 = cv.x; c1 = cv.y;
    }
    if ((unsigned)r0 < (unsigned)NN && (unsigned)c0 < (unsigned)NN) {
        int s = atomicAdd(&g_cursor[r0], 1);
        if (s < PAD) g_ell[(size_t)r0 * PAD + s] = c0;
    }
    if ((unsigned)r1 < (unsigned)NN && (unsigned)c1 < (unsigned)NN) {
        int s = atomicAdd(&g_cursor[r1], 1);
        if (s < PAD) g_ell[(size_t)r1 * PAD + s] = c1;
    }
}

// ---------------- aggregate: warp/node, shuffle-broadcast neighbor chunks ---
// Softmax without max-shift (shift-invariant; logits O(1)).
__global__ void k_agg(const float* __restrict__ bias, float* __restrict__ out) {
    const int gw = (blockIdx.x * blockDim.x + threadIdx.x) >> 5;
    const int lane = threadIdx.x & 31;
    if (gw >= NN) return;
    const int hd = lane >> 3;
    const int cnt = min(__ldg(&g_cursor[gw]), PAD);
    const int* __restrict__ row = &g_ell[(size_t)gw * PAD];
    const float es = __ldg(&g_esrc[gw * HEADS + hd]);

    float a0 = 0.f, a1 = 0.f, a2 = 0.f, a3 = 0.f, d = 0.f;
    const uint2* __restrict__ hb = (const uint2*)g_h16;

    for (int eb = 0; eb < cnt; eb += 32) {
        // one coalesced load of up to 32 neighbor ids, then register broadcast
        int myc = (eb + lane < cnt) ? __ldg(&row[eb + lane]) : 0;
        int m = min(32, cnt - eb);
#pragma unroll 4
        for (int j = 0; j < m; j++) {
            int c = __shfl_sync(0xffffffffu, myc, j);
            float ed = __ldg(&g_edst[c * HEADS + hd]);
            uint2 hv = __ldg(&hb[(size_t)c * 32 + lane]);
            float z = es + ed;
            z = fmaxf(z, 0.2f * z);                      // exact leaky relu
            z = __expf(z);
            float2 f0 = __half22float2(*(const __half2*)&hv.x);
            float2 f1 = __half22float2(*(const __half2*)&hv.y);
            a0 += z * f0.x; a1 += z * f0.y;
            a2 += z * f1.x; a3 += z * f1.y;
            d  += z;
        }
    }

    float inv = 1.f / (d + 1e-16f);
    float4 b4 = __ldg((const float4*)&bias[4 * lane]);
    float4 o;
    o.x = a0 * inv + b4.x;
    o.y = a1 * inv + b4.y;
    o.z = a2 * inv + b4.z;
    o.w = a3 * inv + b4.w;
    ((float4*)out)[(size_t)gw * 32 + lane] = o;
}

// ---------------- launch: ELL build (side) || tensor GEMM (main) -------------
extern "C" void kernel_launch(void* const* d_in, const int* in_sizes, int n_in,
                              void* d_out, int out_size) {
    const float* x    = (const float*)d_in[0];
    const int*   idx  = (const int*)d_in[1];
    const float* W    = (const float*)d_in[2];
    const float* att  = (const float*)d_in[3];
    const float* bias = (const float*)d_in[4];
    float*       out  = (float*)d_out;

    void* curp = 0;
    cudaGetSymbolAddress(&curp, g_cursor);

    const bool forked = (s_side != 0 && s_fork != 0 && s_join != 0);
    cudaStream_t cs = forked ? s_side : (cudaStream_t)0;

    if (forked) {
        cudaEventRecord(s_fork, 0);
        cudaStreamWaitEvent(s_side, s_fork, 0);
    }
    // ELL build on side stream: memset + one pass
    cudaMemsetAsync(curp, 0, NN * sizeof(int), cs);
    k_fill<<<(NE / 2 + 255) / 256, 256, 0, cs>>>(idx);
    if (forked) cudaEventRecord(s_join, s_side);

    // tensor-core GEMM on main stream, starts immediately
    k_gemm<<<(NN + 63) / 64, 128>>>(x, W, att);

    if (forked) cudaStreamWaitEvent((cudaStream_t)0, s_join, 0);
    k_agg<<<(NN * 32 + 255) / 256, 256>>>(bias, out);
}

// round 9
// speedup vs baseline: 1.0869x; 1.0869x over previous
#include <cuda_runtime.h>
#include <cuda_fp16.h>
#include <mma.h>

using namespace nvcuda;

#define NN 50000
#define NE 1600000
#define CD 128      // HEADS * OUT_F
#define HEADS 4
#define PAD 128     // ELL row width; P(deg>128) ~ 1e-40 for Poisson(32)

// smem strides (floats) — non-power-of-two to avoid wmma bank conflicts
#define XS_LD 36    // A tile leading dim (64 x 36)
#define WS_LD 132   // B tile leading dim (32 x 132)
#define EP_LD 132   // epilogue leading dim (16 x 132 per warp)

// ---------------- device-global scratch (no allocations allowed) ------------
__device__ __half g_h16[(size_t)NN * CD];   // 12.8 MB fp16 features
__device__ float  g_esrc[NN * HEADS];
__device__ float  g_edst[NN * HEADS];
__device__ int    g_cursor[NN];
__device__ int    g_ell[(size_t)NN * PAD];  // 25.6 MB ELL neighbor lists

// ---------------- static host resources --------------------------------------
static cudaStream_t s_side = 0;
static cudaEvent_t  s_fork = 0, s_join = 0;
namespace {
struct StreamInit {
    StreamInit() {
        cudaStreamCreateWithFlags(&s_side, cudaStreamNonBlocking);
        cudaEventCreateWithFlags(&s_fork, cudaEventDisableTiming);
        cudaEventCreateWithFlags(&s_join, cudaEventDisableTiming);
    }
};
StreamInit s_init_;
}

// ---------------- tf32 tensor-core GEMM + logits (padded smem strides) -------
// 128 threads (4 warps). Block tile 64 rows x 128 cols, K=128 in 4 chunks of 32.
__global__ __launch_bounds__(128) void k_gemm(const float* __restrict__ x,
                                              const float* __restrict__ W,
                                              const float* __restrict__ att) {
    __shared__ float sm[4 * 16 * EP_LD];       // 8448 floats = 33.8 KB
    float* xs = sm;                            // 64 x XS_LD = 2304
    float* Ws = sm + 64 * XS_LD;               // 32 x WS_LD = 4224 (total 6528)

    const int t = threadIdx.x;
    const int w = t >> 5, lane = t & 31;
    const int R0 = blockIdx.x * 64;

    wmma::fragment<wmma::accumulator, 16, 16, 8, float> acc[8];
#pragma unroll
    for (int c = 0; c < 8; c++) wmma::fill_fragment(acc[c], 0.f);

    for (int kc = 0; kc < 4; kc++) {
        __syncthreads();
        // x tile: 64 rows x 32 k -> 512 float4
#pragma unroll
        for (int j = 0; j < 4; j++) {
            int i = t + 128 * j;
            int row = i >> 3, kq = i & 7;
            int n = R0 + row;
            float4 v = (n < NN) ? __ldg((const float4*)&x[(size_t)n * CD + kc * 32 + kq * 4])
                                : make_float4(0.f, 0.f, 0.f, 0.f);
            *(float4*)&xs[row * XS_LD + kq * 4] = v;
        }
        // W tile: 32 rows x 128 cols -> 1024 float4
#pragma unroll
        for (int j = 0; j < 8; j++) {
            int i = t + 128 * j;
            int kr = i >> 5, c4 = i & 31;
            *(float4*)&Ws[kr * WS_LD + c4 * 4] =
                __ldg((const float4*)&W[(size_t)(kc * 32 + kr) * CD + c4 * 4]);
        }
        __syncthreads();

#pragma unroll
        for (int k0 = 0; k0 < 32; k0 += 8) {
            wmma::fragment<wmma::matrix_a, 16, 16, 8, wmma::precision::tf32, wmma::row_major> af;
            wmma::load_matrix_sync(af, &xs[w * 16 * XS_LD + k0], XS_LD);
#pragma unroll
            for (int i = 0; i < af.num_elements; i++)
                af.x[i] = wmma::__float_to_tf32(af.x[i]);
#pragma unroll
            for (int c = 0; c < 8; c++) {
                wmma::fragment<wmma::matrix_b, 16, 16, 8, wmma::precision::tf32, wmma::row_major> bf;
                wmma::load_matrix_sync(bf, &Ws[k0 * WS_LD + c * 16], WS_LD);
#pragma unroll
                for (int i = 0; i < bf.num_elements; i++)
                    bf.x[i] = wmma::__float_to_tf32(bf.x[i]);
                wmma::mma_sync(acc[c], af, bf, acc[c]);
            }
        }
    }

    // epilogue: each warp dumps its 16x128 block (stride EP_LD) to its region
    __syncthreads();
    float* ep = sm + w * 16 * EP_LD;
#pragma unroll
    for (int c = 0; c < 8; c++)
        wmma::store_matrix_sync(&ep[c * 16], acc[c], EP_LD, wmma::mem_row_major);
    __syncwarp();

    // fp16 h rows: lane l covers features 4l..4l+3
#pragma unroll
    for (int rr = 0; rr < 16; rr++) {
        int n = R0 + w * 16 + rr;
        if (n >= NN) break;
        const float* rowp = &ep[rr * EP_LD + lane * 4];
        __half2 h0 = __floats2half2_rn(rowp[0], rowp[1]);
        __half2 h1 = __floats2half2_rn(rowp[2], rowp[3]);
        uint2 pk;
        pk.x = *(const unsigned*)&h0;
        pk.y = *(const unsigned*)&h1;
        ((uint2*)&g_h16[(size_t)n * CD])[lane] = pk;
    }
    // logits: 64 (row,head) pairs per warp -> 2 per lane
#pragma unroll
    for (int q = 0; q < 2; q++) {
        int p = lane + 32 * q;
        int rr = p >> 2, hd = p & 3;
        int n = R0 + w * 16 + rr;
        if (n >= NN) continue;
        const float* rowp = &ep[rr * EP_LD + hd * 32];
        float es = 0.f, ed = 0.f;
#pragma unroll
        for (int c = 0; c < 32; c++) {
            float v = rowp[c];
            es += v * __ldg(&att[hd * 64 + c]);
            ed += v * __ldg(&att[hd * 64 + 32 + c]);
        }
        g_esrc[n * HEADS + hd] = es;
        g_edst[n * HEADS + hd] = ed;
    }
}

// ---------------- ELL build: single pass, inline dtype detect ----------------
__global__ void k_fill(const int* __restrict__ idx32) {
    int e = 2 * (blockIdx.x * blockDim.x + threadIdx.x);
    if (e >= NE) return;
    // int64 indices < 50000 => high words zero; two-word test, fp prob ~4e-10
    const bool is64 = (__ldg(&idx32[1]) == 0) && (__ldg(&idx32[3]) == 0);
    int r0, r1, c0, c1;
    if (is64) {
        int4 rv = __ldg((const int4*)&idx32[2 * e]);
        int4 cv = __ldg((const int4*)&idx32[2 * (NE + e)]);
        r0 = rv.x; r1 = rv.z; c0 = cv.x; c1 = cv.z;
    } else {
        int2 rv = __ldg((const int2*)&idx32[e]);
        int2 cv = __ldg((const int2*)&idx32[NE + e]);
        r0 = rv.x; r1 = rv.y; c0 = cv.x; c1 = cv.y;
    }
    if ((unsigned)r0 < (unsigned)NN && (unsigned)c0 < (unsigned)NN) {
        int s = atomicAdd(&g_cursor[r0], 1);
        if (s < PAD) g_ell[(size_t)r0 * PAD + s] = c0;
    }
    if ((unsigned)r1 < (unsigned)NN && (unsigned)c1 < (unsigned)NN) {
        int s = atomicAdd(&g_cursor[r1], 1);
        if (s < PAD) g_ell[(size_t)r1 * PAD + s] = c1;
    }
}

// ---------------- aggregate: warp/node, shuffle-broadcast neighbor chunks ---
// Softmax without max-shift (shift-invariant; logits O(1)).
__global__ void k_agg(const float* __restrict__ bias, float* __restrict__ out) {
    const int gw = (blockIdx.x * blockDim.x + threadIdx.x) >> 5;
    const int lane = threadIdx.x & 31;
    if (gw >= NN) return;
    const int hd = lane >> 3;
    const int cnt = min(__ldg(&g_cursor[gw]), PAD);
    const int* __restrict__ row = &g_ell[(size_t)gw * PAD];
    const float es = __ldg(&g_esrc[gw * HEADS + hd]);

    float a0 = 0.f, a1 = 0.f, a2 = 0.f, a3 = 0.f, d = 0.f;
    const uint2* __restrict__ hb = (const uint2*)g_h16;

    for (int eb = 0; eb < cnt; eb += 32) {
        int myc = (eb + lane < cnt) ? __ldg(&row[eb + lane]) : 0;
        int m = min(32, cnt - eb);
        if (m == 32) {
            // full chunk: branchless, deep-unrolled (batched LDGs, MLP~16)
#pragma unroll 8
            for (int j = 0; j < 32; j++) {
                int c = __shfl_sync(0xffffffffu, myc, j);
                float ed = __ldg(&g_edst[c * HEADS + hd]);
                uint2 hv = __ldg(&hb[(size_t)c * 32 + lane]);
                float z = es + ed;
                z = fmaxf(z, 0.2f * z);                  // exact leaky relu
                z = __expf(z);
                float2 f0 = __half22float2(*(const __half2*)&hv.x);
                float2 f1 = __half22float2(*(const __half2*)&hv.y);
                a0 += z * f0.x; a1 += z * f0.y;
                a2 += z * f1.x; a3 += z * f1.y;
                d  += z;
            }
        } else {
#pragma unroll 4
            for (int j = 0; j < m; j++) {
                int c = __shfl_sync(0xffffffffu, myc, j);
                float ed = __ldg(&g_edst[c * HEADS + hd]);
                uint2 hv = __ldg(&hb[(size_t)c * 32 + lane]);
                float z = es + ed;
                z = fmaxf(z, 0.2f * z);
                z = __expf(z);
                float2 f0 = __half22float2(*(const __half2*)&hv.x);
                float2 f1 = __half22float2(*(const __half2*)&hv.y);
                a0 += z * f0.x; a1 += z * f0.y;
                a2 += z * f1.x; a3 += z * f1.y;
                d  += z;
            }
        }
    }

    float inv = 1.f / (d + 1e-16f);
    float4 b4 = __ldg((const float4*)&bias[4 * lane]);
    float4 o;
    o.x = a0 * inv + b4.x;
    o.y = a1 * inv + b4.y;
    o.z = a2 * inv + b4.z;
    o.w = a3 * inv + b4.w;
    ((float4*)out)[(size_t)gw * 32 + lane] = o;
}

// ---------------- launch: ELL build (side) || tensor GEMM (main) -------------
extern "C" void kernel_launch(void* const* d_in, const int* in_sizes, int n_in,
                              void* d_out, int out_size) {
    const float* x    = (const float*)d_in[0];
    const int*   idx  = (const int*)d_in[1];
    const float* W    = (const float*)d_in[2];
    const float* att  = (const float*)d_in[3];
    const float* bias = (const float*)d_in[4];
    float*       out  = (float*)d_out;

    void* curp = 0;
    cudaGetSymbolAddress(&curp, g_cursor);

    const bool forked = (s_side != 0 && s_fork != 0 && s_join != 0);
    cudaStream_t cs = forked ? s_side : (cudaStream_t)0;

    if (forked) {
        cudaEventRecord(s_fork, 0);
        cudaStreamWaitEvent(s_side, s_fork, 0);
    }
    cudaMemsetAsync(curp, 0, NN * sizeof(int), cs);
    k_fill<<<(NE / 2 + 255) / 256, 256, 0, cs>>>(idx);
    if (forked) cudaEventRecord(s_join, s_side);

    k_gemm<<<(NN + 63) / 64, 128>>>(x, W, att);

    if (forked) cudaStreamWaitEvent((cudaStream_t)0, s_join, 0);
    k_agg<<<(NN * 32 + 255) / 256, 256>>>(bias, out);
}